// round 11
// baseline (speedup 1.0000x reference)
#include <cuda_runtime.h>
#include <cuda_bf16.h>
#include <cstdint>

// Histogram_15126874816754:
//   out[b, (p>0), y, x] += |p|/STD  over N events, then clip at 1.0.
// Settled structure (scatter at the divergent-atomic wavefront floor):
//   memsetAsync zero (DMA fill; lines land dirty in L2)
//   -> red scatter (__ldcs streaming inputs, evict_last REDs re-pin lines)
//   -> clip (L2-resident __ldcg reads, conditional stores).
// R7/R8: value-returning atomics ~60% slower than red -> rejected.
// R4: grid-stride zero slower than flat -> rejected.
// R10 experiment: DMA memset vs store-zero (isolating the L2-pinning theory).

#define INV_STD_C  (1.0f / 20.0f)
#define CLIP_MAX_C 1.0f

__device__ __forceinline__ uint64_t make_evict_last_policy() {
    uint64_t pol;
    asm("createpolicy.fractional.L2::evict_last.b64 %0, 1.0;" : "=l"(pol));
    return pol;
}

// fire-and-forget RED with L2 evict_last hint (pins touched image lines)
__device__ __forceinline__ void red_add_f32_evict_last(float* p, float v, uint64_t pol) {
    asm volatile(
        "red.relaxed.gpu.global.L2::cache_hint.add.f32 [%0], %1, %2;"
        :: "l"(p), "f"(v), "l"(pol) : "memory");
}

// ---------------------------------------------------------------------------
// Scatter: 8 events/thread, front-batched __ldcs input loads (evict-first),
// RED.E.ADD.F32 with evict_last. At the divergent-atomic wavefront floor.
// ---------------------------------------------------------------------------
__global__ void __launch_bounds__(256)
hist_scatter_kernel(const int4* __restrict__ xs,
                    const int4* __restrict__ ys,
                    const float4* __restrict__ ps,
                    const int4* __restrict__ bs,
                    const int* __restrict__ wp,
                    const int* __restrict__ hp,
                    float* __restrict__ out,
                    int n8)
{
    const int W = __ldg(wp);
    const int H = __ldg(hp);
    const uint64_t pol = make_evict_last_policy();

    const int i = blockIdx.x * blockDim.x + threadIdx.x;
    if (i >= n8) return;

    const int4   x0 = __ldcs(xs + 2 * i),  x1 = __ldcs(xs + 2 * i + 1);
    const int4   y0 = __ldcs(ys + 2 * i),  y1 = __ldcs(ys + 2 * i + 1);
    const float4 p0 = __ldcs(ps + 2 * i),  p1 = __ldcs(ps + 2 * i + 1);
    const int4   b0 = __ldcs(bs + 2 * i),  b1 = __ldcs(bs + 2 * i + 1);

#define SCATTER_ONE(xx, yy, pp, bb)                                        \
    {                                                                      \
        const int pos = (pp) > 0.0f;                                       \
        const int idx = (((bb) * 2 + pos) * H + (yy)) * W + (xx);          \
        red_add_f32_evict_last(out + idx, fabsf(pp) * INV_STD_C, pol);     \
    }

    SCATTER_ONE(x0.x, y0.x, p0.x, b0.x)
    SCATTER_ONE(x0.y, y0.y, p0.y, b0.y)
    SCATTER_ONE(x0.z, y0.z, p0.z, b0.z)
    SCATTER_ONE(x0.w, y0.w, p0.w, b0.w)
    SCATTER_ONE(x1.x, y1.x, p1.x, b1.x)
    SCATTER_ONE(x1.y, y1.y, p1.y, b1.y)
    SCATTER_ONE(x1.z, y1.z, p1.z, b1.z)
    SCATTER_ONE(x1.w, y1.w, p1.w, b1.w)
#undef SCATTER_ONE
}

__global__ void
hist_scatter_tail_kernel(const int* __restrict__ xs,
                         const int* __restrict__ ys,
                         const float* __restrict__ ps,
                         const int* __restrict__ bs,
                         const int* __restrict__ wp,
                         const int* __restrict__ hp,
                         float* __restrict__ out,
                         int start, int n)
{
    const int k = start + blockIdx.x * blockDim.x + threadIdx.x;
    if (k >= n) return;
    const int W = __ldg(wp);
    const int H = __ldg(hp);
    const float pk = ps[k];
    const int pos = pk > 0.0f;
    const int idx = ((bs[k] * 2 + pos) * H + ys[k]) * W + xs[k];
    atomicAdd(out + idx, fabsf(pk) * INV_STD_C);
}

// ---------------------------------------------------------------------------
// Clip: one float4/thread, __ldcg reads (image mostly L2-resident), store
// only if a component exceeds 1.0 (rare) -> write stream ~vanishes.
// ---------------------------------------------------------------------------
__global__ void __launch_bounds__(256)
hist_clip_kernel(float* __restrict__ out, int n)
{
    const int n4 = n >> 2;
    const int i = blockIdx.x * blockDim.x + threadIdx.x;

    if (i < n4) {
        float4* o4 = reinterpret_cast<float4*>(out);
        float4 v = __ldcg(o4 + i);
        if (v.x > CLIP_MAX_C || v.y > CLIP_MAX_C ||
            v.z > CLIP_MAX_C || v.w > CLIP_MAX_C) {
            v.x = fminf(v.x, CLIP_MAX_C);
            v.y = fminf(v.y, CLIP_MAX_C);
            v.z = fminf(v.z, CLIP_MAX_C);
            v.w = fminf(v.w, CLIP_MAX_C);
            o4[i] = v;
        }
    } else if (i == n4) {
        for (int k = n4 * 4; k < n; ++k) {
            const float v = out[k];
            if (v > CLIP_MAX_C) out[k] = CLIP_MAX_C;
        }
    }
}

// ---------------------------------------------------------------------------
extern "C" void kernel_launch(void* const* d_in, const int* in_sizes, int n_in,
                              void* d_out, int out_size)
{
    const int*   xs = (const int*)  d_in[0];
    const int*   ys = (const int*)  d_in[1];
    const float* ps = (const float*)d_in[2];
    const int*   bs = (const int*)  d_in[3];
    const int*   wp = (const int*)  d_in[4];
    const int*   hp = (const int*)  d_in[5];

    float* out = (float*)d_out;
    const int n = in_sizes[0];

    // 1) zero image via DMA fill (graph-capturable)
    cudaMemsetAsync(d_out, 0, (size_t)out_size * sizeof(float), 0);

    // 2) scatter-add (red, 8 events/thread)
    {
        const int n8 = n >> 3;
        if (n8 > 0) {
            const int blocks = (n8 + 255) / 256;
            hist_scatter_kernel<<<blocks, 256>>>(
                (const int4*)xs, (const int4*)ys, (const float4*)ps,
                (const int4*)bs, wp, hp, out, n8);
        }
        if (n & 7) {
            hist_scatter_tail_kernel<<<1, 32>>>(xs, ys, ps, bs, wp, hp,
                                                out, n & ~7, n);
        }
    }

    // 3) clip (conditional store)
    {
        const int n4 = out_size >> 2;
        const int total_threads = n4 + ((out_size & 3) ? 1 : 0);
        const int blocks = (total_threads + 255) / 256;
        hist_clip_kernel<<<blocks, 256>>>(out, out_size);
    }
}

// round 12
// speedup vs baseline: 1.0233x; 1.0233x over previous
#include <cuda_runtime.h>
#include <cuda_bf16.h>
#include <cstdint>

// Histogram_15126874816754:
//   out[b, (p>0), y, x] += |p|/STD  over N events, then clip at 1.0.
// Settled facts:
//   R7/R8: value-returning atomics ~60% slower than red -> use red.
//   R11: store-zero with evict_last is load-bearing (memset -> clip goes
//        DRAM-bound, +9us). Keep store-zero.
//   R9: scatter is at the divergent-atomic wavefront floor (~57us).
// This round: PDL overlap. Scatter launches programmatically while zero is
// still running, streams all event inputs (independent of zero), then
// cudaGridDependencySynchronize() gates the REDs on zero completion.

#define INV_STD_C  (1.0f / 20.0f)
#define CLIP_MAX_C 1.0f

__device__ __forceinline__ uint64_t make_evict_last_policy() {
    uint64_t pol;
    asm("createpolicy.fractional.L2::evict_last.b64 %0, 1.0;" : "=l"(pol));
    return pol;
}

// fire-and-forget RED with L2 evict_last hint (keeps image resident)
__device__ __forceinline__ void red_add_f32_evict_last(float* p, float v, uint64_t pol) {
    asm volatile(
        "red.relaxed.gpu.global.L2::cache_hint.add.f32 [%0], %1, %2;"
        :: "l"(p), "f"(v), "l"(pol) : "memory");
}

__device__ __forceinline__ void st_zero4_evict_last(float4* p, uint64_t pol) {
    const float z = 0.0f;
    asm volatile(
        "st.global.L2::cache_hint.v4.f32 [%0], {%1, %1, %1, %1}, %2;"
        :: "l"(p), "f"(z), "l"(pol) : "memory");
}

// ---------------------------------------------------------------------------
// Zero pass: one float4/thread, evict_last stores (pins image in L2).
// ---------------------------------------------------------------------------
__global__ void __launch_bounds__(256)
hist_zero_kernel(float* __restrict__ out, int n)
{
    const int n4 = n >> 2;
    const int i = blockIdx.x * blockDim.x + threadIdx.x;
    const uint64_t pol = make_evict_last_policy();

    if (i < n4) {
        st_zero4_evict_last(reinterpret_cast<float4*>(out) + i, pol);
    } else if (i == n4) {
        for (int k = n4 * 4; k < n; ++k) out[k] = 0.0f;
    }
}

// ---------------------------------------------------------------------------
// Scatter (PDL secondary): streams all inputs and computes idx/val BEFORE
// cudaGridDependencySynchronize(), so that work overlaps the zero pass.
// REDs are issued only after the dependency resolves (zero complete).
// ---------------------------------------------------------------------------
__global__ void __launch_bounds__(256)
hist_scatter_kernel(const int4* __restrict__ xs,
                    const int4* __restrict__ ys,
                    const float4* __restrict__ ps,
                    const int4* __restrict__ bs,
                    const int* __restrict__ wp,
                    const int* __restrict__ hp,
                    float* __restrict__ out,
                    int n8)
{
    const int i = blockIdx.x * blockDim.x + threadIdx.x;
    const uint64_t pol = make_evict_last_policy();

    int   idx[8];
    float val[8];
    bool  active = (i < n8);

    if (active) {
        const int W = __ldg(wp);
        const int H = __ldg(hp);

        const int4   x0 = __ldcs(xs + 2 * i),  x1 = __ldcs(xs + 2 * i + 1);
        const int4   y0 = __ldcs(ys + 2 * i),  y1 = __ldcs(ys + 2 * i + 1);
        const float4 p0 = __ldcs(ps + 2 * i),  p1 = __ldcs(ps + 2 * i + 1);
        const int4   b0 = __ldcs(bs + 2 * i),  b1 = __ldcs(bs + 2 * i + 1);

        const int   xa[8] = {x0.x, x0.y, x0.z, x0.w, x1.x, x1.y, x1.z, x1.w};
        const int   ya[8] = {y0.x, y0.y, y0.z, y0.w, y1.x, y1.y, y1.z, y1.w};
        const float pa[8] = {p0.x, p0.y, p0.z, p0.w, p1.x, p1.y, p1.z, p1.w};
        const int   ba[8] = {b0.x, b0.y, b0.z, b0.w, b1.x, b1.y, b1.z, b1.w};
#pragma unroll
        for (int j = 0; j < 8; ++j) {
            const int pos = pa[j] > 0.0f;
            idx[j] = ((ba[j] * 2 + pos) * H + ya[j]) * W + xa[j];
            val[j] = fabsf(pa[j]) * INV_STD_C;
        }
    }

    // Wait for the zero pass to finish before touching the image.
    cudaGridDependencySynchronize();

    if (active) {
#pragma unroll
        for (int j = 0; j < 8; ++j)
            red_add_f32_evict_last(out + idx[j], val[j], pol);
    }
}

__global__ void
hist_scatter_tail_kernel(const int* __restrict__ xs,
                         const int* __restrict__ ys,
                         const float* __restrict__ ps,
                         const int* __restrict__ bs,
                         const int* __restrict__ wp,
                         const int* __restrict__ hp,
                         float* __restrict__ out,
                         int start, int n)
{
    const int k = start + blockIdx.x * blockDim.x + threadIdx.x;
    if (k >= n) return;
    const int W = __ldg(wp);
    const int H = __ldg(hp);
    const float pk = ps[k];
    const int pos = pk > 0.0f;
    const int idx = ((bs[k] * 2 + pos) * H + ys[k]) * W + xs[k];
    atomicAdd(out + idx, fabsf(pk) * INV_STD_C);
}

// ---------------------------------------------------------------------------
// Clip (PDL secondary after scatter): sync first (loads must see final
// sums), then L2-resident reads, conditional stores.
// ---------------------------------------------------------------------------
__global__ void __launch_bounds__(256)
hist_clip_kernel(float* __restrict__ out, int n)
{
    const int n4 = n >> 2;
    const int i = blockIdx.x * blockDim.x + threadIdx.x;

    cudaGridDependencySynchronize();

    if (i < n4) {
        float4* o4 = reinterpret_cast<float4*>(out);
        float4 v = __ldcg(o4 + i);
        if (v.x > CLIP_MAX_C || v.y > CLIP_MAX_C ||
            v.z > CLIP_MAX_C || v.w > CLIP_MAX_C) {
            v.x = fminf(v.x, CLIP_MAX_C);
            v.y = fminf(v.y, CLIP_MAX_C);
            v.z = fminf(v.z, CLIP_MAX_C);
            v.w = fminf(v.w, CLIP_MAX_C);
            o4[i] = v;
        }
    } else if (i == n4) {
        for (int k = n4 * 4; k < n; ++k) {
            const float v = out[k];
            if (v > CLIP_MAX_C) out[k] = CLIP_MAX_C;
        }
    }
}

// ---------------------------------------------------------------------------
extern "C" void kernel_launch(void* const* d_in, const int* in_sizes, int n_in,
                              void* d_out, int out_size)
{
    const int*   xs = (const int*)  d_in[0];
    const int*   ys = (const int*)  d_in[1];
    const float* ps = (const float*)d_in[2];
    const int*   bs = (const int*)  d_in[3];
    const int*   wp = (const int*)  d_in[4];
    const int*   hp = (const int*)  d_in[5];

    float* out = (float*)d_out;
    const int n = in_sizes[0];

    // 1) zero image (evict_last stores -> L2-resident)
    {
        const int n4 = out_size >> 2;
        const int total_threads = n4 + ((out_size & 3) ? 1 : 0);
        const int blocks = (total_threads + 255) / 256;
        hist_zero_kernel<<<blocks, 256>>>(out, out_size);
    }

    // 2) scatter-add, PDL-overlapped with the zero pass
    {
        const int n8 = n >> 3;
        if (n8 > 0) {
            const int blocks = (n8 + 255) / 256;

            cudaLaunchConfig_t cfg = {};
            cfg.gridDim  = dim3(blocks, 1, 1);
            cfg.blockDim = dim3(256, 1, 1);
            cfg.dynamicSmemBytes = 0;
            cfg.stream = 0;
            cudaLaunchAttribute attr[1];
            attr[0].id = cudaLaunchAttributeProgrammaticStreamSerialization;
            attr[0].val.programmaticStreamSerializationAllowed = 1;
            cfg.attrs = attr;
            cfg.numAttrs = 1;

            cudaLaunchKernelEx(&cfg, hist_scatter_kernel,
                               (const int4*)xs, (const int4*)ys,
                               (const float4*)ps, (const int4*)bs,
                               wp, hp, out, n8);
        }
        if (n & 7) {
            hist_scatter_tail_kernel<<<1, 32>>>(xs, ys, ps, bs, wp, hp,
                                                out, n & ~7, n);
        }
    }

    // 3) clip, PDL-launched (hides launch latency behind scatter tail)
    {
        const int n4 = out_size >> 2;
        const int total_threads = n4 + ((out_size & 3) ? 1 : 0);
        const int blocks = (total_threads + 255) / 256;

        cudaLaunchConfig_t cfg = {};
        cfg.gridDim  = dim3(blocks, 1, 1);
        cfg.blockDim = dim3(256, 1, 1);
        cfg.dynamicSmemBytes = 0;
        cfg.stream = 0;
        cudaLaunchAttribute attr[1];
        attr[0].id = cudaLaunchAttributeProgrammaticStreamSerialization;
        attr[0].val.programmaticStreamSerializationAllowed = 1;
        cfg.attrs = attr;
        cfg.numAttrs = 1;

        cudaLaunchKernelEx(&cfg, hist_clip_kernel, out, out_size);
    }
}